// round 3
// baseline (speedup 1.0000x reference)
#include <cuda_runtime.h>

// Problem dims (fixed by the dataset)
static constexpr int B_ = 4;
static constexpr int S_ = 4096;
static constexpr int D_ = 512;

// Scratch: __device__ globals (allocation inside kernel_launch is forbidden)
__device__ float g_Q[(size_t)B_ * S_ * D_];   // 32 MB
__device__ float g_K[(size_t)B_ * S_ * D_];   // 32 MB
__device__ float g_V[(size_t)B_ * S_ * D_];   // 32 MB
__device__ float g_P[(size_t)B_ * S_ * S_];   // 256 MB (scores -> probs in place)

// ---------------------------------------------------------------------------
// Tiled fp32 GEMM: C[M,N] = alpha * A[M,K] @ op(B) (+ bias)
//   TRANSB=false: B is [K,N] row-major (NN)
//   TRANSB=true : B is [N,K] row-major (NT, i.e. C = A @ B^T)
// 128x128 CTA tile, BK=16, 256 threads, 8x8 per-thread microtile,
// float4 global loads with register prefetch across K-tiles.
// All of M,N,K are multiples of the tile sizes here -> no bounds checks.
// grid.z batches via element strides sA/sB/sC.
// ---------------------------------------------------------------------------
template <bool TRANSB, bool BIAS>
__global__ __launch_bounds__(256, 2)
void gemm128(const float* __restrict__ A, const float* __restrict__ Bm,
             const float* __restrict__ bias, float* __restrict__ C,
             int M, int N, int K,
             long long sA, long long sB, long long sC, float alpha)
{
    constexpr int BM = 128, BN = 128, BK = 16;
    constexpr int LDS = 132;  // +4 pad: 16B-aligned rows, breaks k-scatter bank conflicts

    __shared__ float As[BK][LDS];
    __shared__ float Bs[BK][LDS];

    const int tid = threadIdx.x;
    const int tx = tid & 15;   // N direction (16)
    const int ty = tid >> 4;   // M direction (16)

    const float* Ab = A  + (long long)blockIdx.z * sA;
    const float* Bb = Bm + (long long)blockIdx.z * sB;
    float*       Cb = C  + (long long)blockIdx.z * sC;

    const int bm = blockIdx.y * BM;
    const int bn = blockIdx.x * BN;

    // A-tile load mapping: 128x16 floats = 512 float4, 2 per thread
    const int a_row = tid >> 2;          // 0..63, +64 for second
    const int a_k   = (tid & 3) << 2;    // 0,4,8,12
    // B-tile NN mapping: 16x128 floats, vectorized along N
    const int bnn_row = tid >> 5;        // 0..7, +8
    const int bnn_col = (tid & 31) << 2; // 0..124
    // B-tile NT mapping: vectorized along K
    const int bnt_n = tid >> 2;          // 0..63, +64
    const int bnt_k = (tid & 3) << 2;    // 0,4,8,12

    float4 aR[2], bR[2];

    auto gload = [&](int kt) {
        #pragma unroll
        for (int i = 0; i < 2; i++)
            aR[i] = *reinterpret_cast<const float4*>(
                &Ab[(long long)(bm + a_row + i * 64) * K + kt + a_k]);
        if (TRANSB) {
            #pragma unroll
            for (int i = 0; i < 2; i++)
                bR[i] = *reinterpret_cast<const float4*>(
                    &Bb[(long long)(bn + bnt_n + i * 64) * K + kt + bnt_k]);
        } else {
            #pragma unroll
            for (int i = 0; i < 2; i++)
                bR[i] = *reinterpret_cast<const float4*>(
                    &Bb[(long long)(kt + bnn_row + i * 8) * N + bn + bnn_col]);
        }
    };

    auto sstore = [&]() {
        #pragma unroll
        for (int i = 0; i < 2; i++) {
            As[a_k + 0][a_row + i * 64] = aR[i].x;
            As[a_k + 1][a_row + i * 64] = aR[i].y;
            As[a_k + 2][a_row + i * 64] = aR[i].z;
            As[a_k + 3][a_row + i * 64] = aR[i].w;
        }
        if (TRANSB) {
            #pragma unroll
            for (int i = 0; i < 2; i++) {
                Bs[bnt_k + 0][bnt_n + i * 64] = bR[i].x;
                Bs[bnt_k + 1][bnt_n + i * 64] = bR[i].y;
                Bs[bnt_k + 2][bnt_n + i * 64] = bR[i].z;
                Bs[bnt_k + 3][bnt_n + i * 64] = bR[i].w;
            }
        } else {
            #pragma unroll
            for (int i = 0; i < 2; i++)
                *reinterpret_cast<float4*>(&Bs[bnn_row + i * 8][bnn_col]) = bR[i];
        }
    };

    float acc[8][8];
    #pragma unroll
    for (int i = 0; i < 8; i++)
        #pragma unroll
        for (int j = 0; j < 8; j++) acc[i][j] = 0.f;

    gload(0);
    sstore();
    __syncthreads();

    const int nT = K / BK;
    for (int t = 0; t < nT; t++) {
        if (t + 1 < nT) gload((t + 1) * BK);

        #pragma unroll
        for (int k = 0; k < BK; k++) {
            float4 a0 = *reinterpret_cast<const float4*>(&As[k][(ty << 2)]);
            float4 a1 = *reinterpret_cast<const float4*>(&As[k][64 + (ty << 2)]);
            float4 b0 = *reinterpret_cast<const float4*>(&Bs[k][(tx << 2)]);
            float4 b1 = *reinterpret_cast<const float4*>(&Bs[k][64 + (tx << 2)]);
            float av[8] = {a0.x, a0.y, a0.z, a0.w, a1.x, a1.y, a1.z, a1.w};
            float bv[8] = {b0.x, b0.y, b0.z, b0.w, b1.x, b1.y, b1.z, b1.w};
            #pragma unroll
            for (int i = 0; i < 8; i++)
                #pragma unroll
                for (int j = 0; j < 8; j++)
                    acc[i][j] = fmaf(av[i], bv[j], acc[i][j]);
        }
        __syncthreads();
        if (t + 1 < nT) {
            sstore();
            __syncthreads();
        }
    }

    // Epilogue: alpha scale (+ bias), vectorized stores
    #pragma unroll
    for (int ih = 0; ih < 2; ih++) {
        #pragma unroll
        for (int i = 0; i < 4; i++) {
            const int row = bm + ih * 64 + (ty << 2) + i;
            #pragma unroll
            for (int jh = 0; jh < 2; jh++) {
                const int col = bn + jh * 64 + (tx << 2);
                float4 r;
                r.x = acc[ih * 4 + i][jh * 4 + 0] * alpha;
                r.y = acc[ih * 4 + i][jh * 4 + 1] * alpha;
                r.z = acc[ih * 4 + i][jh * 4 + 2] * alpha;
                r.w = acc[ih * 4 + i][jh * 4 + 3] * alpha;
                if (BIAS) {
                    r.x += __ldg(&bias[col + 0]);
                    r.y += __ldg(&bias[col + 1]);
                    r.z += __ldg(&bias[col + 2]);
                    r.w += __ldg(&bias[col + 3]);
                }
                *reinterpret_cast<float4*>(&Cb[(long long)row * N + col]) = r;
            }
        }
    }
}

// ---------------------------------------------------------------------------
// In-place row softmax over rows of length 4096. One 256-thread CTA per row;
// the whole row lives in registers (16 floats/thread) -> single read, single write.
// ---------------------------------------------------------------------------
__global__ __launch_bounds__(256)
void softmax4096(float* __restrict__ P)
{
    __shared__ float redm[8];
    __shared__ float reds[8];

    const long long row = blockIdx.x;
    float4* p = reinterpret_cast<float4*>(P + row * (long long)S_);
    const int tid = threadIdx.x;

    float4 v[4];
    float m = -3.0e38f;
    #pragma unroll
    for (int i = 0; i < 4; i++) {
        v[i] = p[tid + i * 256];
        m = fmaxf(m, fmaxf(fmaxf(v[i].x, v[i].y), fmaxf(v[i].z, v[i].w)));
    }
    #pragma unroll
    for (int o = 16; o; o >>= 1) m = fmaxf(m, __shfl_xor_sync(0xffffffffu, m, o));
    if ((tid & 31) == 0) redm[tid >> 5] = m;
    __syncthreads();
    m = redm[0];
    #pragma unroll
    for (int i = 1; i < 8; i++) m = fmaxf(m, redm[i]);

    float s = 0.f;
    #pragma unroll
    for (int i = 0; i < 4; i++) {
        v[i].x = __expf(v[i].x - m);
        v[i].y = __expf(v[i].y - m);
        v[i].z = __expf(v[i].z - m);
        v[i].w = __expf(v[i].w - m);
        s += v[i].x + v[i].y + v[i].z + v[i].w;
    }
    #pragma unroll
    for (int o = 16; o; o >>= 1) s += __shfl_xor_sync(0xffffffffu, s, o);
    if ((tid & 31) == 0) reds[tid >> 5] = s;
    __syncthreads();
    s = 0.f;
    #pragma unroll
    for (int i = 0; i < 8; i++) s += reds[i];

    const float inv = 1.0f / s;
    #pragma unroll
    for (int i = 0; i < 4; i++) {
        v[i].x *= inv; v[i].y *= inv; v[i].z *= inv; v[i].w *= inv;
        p[tid + i * 256] = v[i];
    }
}

// ---------------------------------------------------------------------------
// Launch: x->(Q,K,V) projections, S = 0.5*Q@K^T, softmax rows, Z = P@V
// ---------------------------------------------------------------------------
extern "C" void kernel_launch(void* const* d_in, const int* /*in_sizes*/, int /*n_in*/,
                              void* d_out, int /*out_size*/)
{
    const float* x  = (const float*)d_in[0];
    const float* Wq = (const float*)d_in[1];
    const float* bq = (const float*)d_in[2];
    const float* Wk = (const float*)d_in[3];
    const float* bk = (const float*)d_in[4];
    const float* Wv = (const float*)d_in[5];
    const float* bv = (const float*)d_in[6];
    float* out = (float*)d_out;

    float *Q, *K, *V, *P;
    cudaGetSymbolAddress((void**)&Q, g_Q);
    cudaGetSymbolAddress((void**)&K, g_K);
    cudaGetSymbolAddress((void**)&V, g_V);
    cudaGetSymbolAddress((void**)&P, g_P);

    const long long dQKV = (long long)S_ * D_;  // per-batch Q/K/V stride
    const long long dP   = (long long)S_ * S_;  // per-batch score stride

    dim3 blk(256);

    // QKV projections: M = B*S = 16384, N = K = 512 (NN, +bias)
    dim3 gProj(D_ / 128, (B_ * S_) / 128, 1);
    gemm128<false, true><<<gProj, blk>>>(x, Wq, bq, Q, B_ * S_, D_, D_, 0, 0, 0, 1.f);
    gemm128<false, true><<<gProj, blk>>>(x, Wk, bk, K, B_ * S_, D_, D_, 0, 0, 0, 1.f);
    gemm128<false, true><<<gProj, blk>>>(x, Wv, bv, V, B_ * S_, D_, D_, 0, 0, 0, 1.f);

    // Scores: per-batch 4096x4096x512, NT, alpha = 1/scale = 0.5
    dim3 gS(S_ / 128, S_ / 128, B_);
    gemm128<true, false><<<gS, blk>>>(Q, K, nullptr, P, S_, S_, D_, dQKV, dQKV, dP, 0.5f);

    // Row softmax (in place)
    softmax4096<<<B_ * S_, 256>>>(P);

    // Z = P @ V: per-batch 4096x512x4096, NN
    dim3 gZ(D_ / 128, S_ / 128, B_);
    gemm128<false, false><<<gZ, blk>>>(P, V, nullptr, out, S_, D_, S_, dP, dQKV, dQKV, 1.f);
}

// round 4
// speedup vs baseline: 1.0013x; 1.0013x over previous
#include <cuda_runtime.h>

// Problem dims (fixed by the dataset)
static constexpr int B_ = 4;
static constexpr int S_ = 4096;
static constexpr int D_ = 512;

// Scratch: __device__ globals (allocation inside kernel_launch is forbidden)
__device__ float g_Q[(size_t)B_ * S_ * D_];   // 32 MB
__device__ float g_K[(size_t)B_ * S_ * D_];   // 32 MB
__device__ float g_V[(size_t)B_ * S_ * D_];   // 32 MB
__device__ float g_P[(size_t)B_ * S_ * S_];   // 256 MB (scores -> probs in place)

// ---------------------------------------------------------------------------
// Tiled fp32 GEMM: C[M,N] = alpha * A[M,K] @ op(B) (+ bias)
//   TRANSB=false: B is [K,N] row-major (NN)
//   TRANSB=true : B is [N,K] row-major (NT, i.e. C = A @ B^T)
// 128x128 CTA tile, BK=16, 256 threads, 8x8 per-thread microtile,
// float4 global loads with register prefetch across K-tiles.
// All of M,N,K are multiples of the tile sizes here -> no bounds checks.
// grid.z batches via element strides sA/sB/sC.
// ---------------------------------------------------------------------------
template <bool TRANSB, bool BIAS>
__global__ __launch_bounds__(256, 2)
void gemm128(const float* __restrict__ A, const float* __restrict__ Bm,
             const float* __restrict__ bias, float* __restrict__ C,
             int M, int N, int K,
             long long sA, long long sB, long long sC, float alpha)
{
    constexpr int BM = 128, BN = 128, BK = 16;
    constexpr int LDS = 132;  // +4 pad: 16B-aligned rows, breaks k-scatter bank conflicts

    __shared__ float As[BK][LDS];
    __shared__ float Bs[BK][LDS];

    const int tid = threadIdx.x;
    const int tx = tid & 15;   // N direction (16)
    const int ty = tid >> 4;   // M direction (16)

    const float* Ab = A  + (long long)blockIdx.z * sA;
    const float* Bb = Bm + (long long)blockIdx.z * sB;
    float*       Cb = C  + (long long)blockIdx.z * sC;

    const int bm = blockIdx.y * BM;
    const int bn = blockIdx.x * BN;

    // A-tile load mapping: 128x16 floats = 512 float4, 2 per thread
    const int a_row = tid >> 2;          // 0..63, +64 for second
    const int a_k   = (tid & 3) << 2;    // 0,4,8,12
    // B-tile NN mapping: 16x128 floats, vectorized along N
    const int bnn_row = tid >> 5;        // 0..7, +8
    const int bnn_col = (tid & 31) << 2; // 0..124
    // B-tile NT mapping: vectorized along K
    const int bnt_n = tid >> 2;          // 0..63, +64
    const int bnt_k = (tid & 3) << 2;    // 0,4,8,12

    float4 aR[2], bR[2];

    auto gload = [&](int kt) {
        #pragma unroll
        for (int i = 0; i < 2; i++)
            aR[i] = *reinterpret_cast<const float4*>(
                &Ab[(long long)(bm + a_row + i * 64) * K + kt + a_k]);
        if (TRANSB) {
            #pragma unroll
            for (int i = 0; i < 2; i++)
                bR[i] = *reinterpret_cast<const float4*>(
                    &Bb[(long long)(bn + bnt_n + i * 64) * K + kt + bnt_k]);
        } else {
            #pragma unroll
            for (int i = 0; i < 2; i++)
                bR[i] = *reinterpret_cast<const float4*>(
                    &Bb[(long long)(kt + bnn_row + i * 8) * N + bn + bnn_col]);
        }
    };

    auto sstore = [&]() {
        #pragma unroll
        for (int i = 0; i < 2; i++) {
            As[a_k + 0][a_row + i * 64] = aR[i].x;
            As[a_k + 1][a_row + i * 64] = aR[i].y;
            As[a_k + 2][a_row + i * 64] = aR[i].z;
            As[a_k + 3][a_row + i * 64] = aR[i].w;
        }
        if (TRANSB) {
            #pragma unroll
            for (int i = 0; i < 2; i++) {
                Bs[bnt_k + 0][bnt_n + i * 64] = bR[i].x;
                Bs[bnt_k + 1][bnt_n + i * 64] = bR[i].y;
                Bs[bnt_k + 2][bnt_n + i * 64] = bR[i].z;
                Bs[bnt_k + 3][bnt_n + i * 64] = bR[i].w;
            }
        } else {
            #pragma unroll
            for (int i = 0; i < 2; i++)
                *reinterpret_cast<float4*>(&Bs[bnn_row + i * 8][bnn_col]) = bR[i];
        }
    };

    float acc[8][8];
    #pragma unroll
    for (int i = 0; i < 8; i++)
        #pragma unroll
        for (int j = 0; j < 8; j++) acc[i][j] = 0.f;

    gload(0);
    sstore();
    __syncthreads();

    const int nT = K / BK;
    for (int t = 0; t < nT; t++) {
        if (t + 1 < nT) gload((t + 1) * BK);

        #pragma unroll
        for (int k = 0; k < BK; k++) {
            float4 a0 = *reinterpret_cast<const float4*>(&As[k][(ty << 2)]);
            float4 a1 = *reinterpret_cast<const float4*>(&As[k][64 + (ty << 2)]);
            float4 b0 = *reinterpret_cast<const float4*>(&Bs[k][(tx << 2)]);
            float4 b1 = *reinterpret_cast<const float4*>(&Bs[k][64 + (tx << 2)]);
            float av[8] = {a0.x, a0.y, a0.z, a0.w, a1.x, a1.y, a1.z, a1.w};
            float bv[8] = {b0.x, b0.y, b0.z, b0.w, b1.x, b1.y, b1.z, b1.w};
            #pragma unroll
            for (int i = 0; i < 8; i++)
                #pragma unroll
                for (int j = 0; j < 8; j++)
                    acc[i][j] = fmaf(av[i], bv[j], acc[i][j]);
        }
        __syncthreads();
        if (t + 1 < nT) {
            sstore();
            __syncthreads();
        }
    }

    // Epilogue: alpha scale (+ bias), vectorized stores
    #pragma unroll
    for (int ih = 0; ih < 2; ih++) {
        #pragma unroll
        for (int i = 0; i < 4; i++) {
            const int row = bm + ih * 64 + (ty << 2) + i;
            #pragma unroll
            for (int jh = 0; jh < 2; jh++) {
                const int col = bn + jh * 64 + (tx << 2);
                float4 r;
                r.x = acc[ih * 4 + i][jh * 4 + 0] * alpha;
                r.y = acc[ih * 4 + i][jh * 4 + 1] * alpha;
                r.z = acc[ih * 4 + i][jh * 4 + 2] * alpha;
                r.w = acc[ih * 4 + i][jh * 4 + 3] * alpha;
                if (BIAS) {
                    r.x += __ldg(&bias[col + 0]);
                    r.y += __ldg(&bias[col + 1]);
                    r.z += __ldg(&bias[col + 2]);
                    r.w += __ldg(&bias[col + 3]);
                }
                *reinterpret_cast<float4*>(&Cb[(long long)row * N + col]) = r;
            }
        }
    }
}

// ---------------------------------------------------------------------------
// In-place row softmax over rows of length 4096. One 256-thread CTA per row;
// the whole row lives in registers (16 floats/thread) -> single read, single write.
// ---------------------------------------------------------------------------
__global__ __launch_bounds__(256)
void softmax4096(float* __restrict__ P)
{
    __shared__ float redm[8];
    __shared__ float reds[8];

    const long long row = blockIdx.x;
    float4* p = reinterpret_cast<float4*>(P + row * (long long)S_);
    const int tid = threadIdx.x;

    float4 v[4];
    float m = -3.0e38f;
    #pragma unroll
    for (int i = 0; i < 4; i++) {
        v[i] = p[tid + i * 256];
        m = fmaxf(m, fmaxf(fmaxf(v[i].x, v[i].y), fmaxf(v[i].z, v[i].w)));
    }
    #pragma unroll
    for (int o = 16; o; o >>= 1) m = fmaxf(m, __shfl_xor_sync(0xffffffffu, m, o));
    if ((tid & 31) == 0) redm[tid >> 5] = m;
    __syncthreads();
    m = redm[0];
    #pragma unroll
    for (int i = 1; i < 8; i++) m = fmaxf(m, redm[i]);

    float s = 0.f;
    #pragma unroll
    for (int i = 0; i < 4; i++) {
        v[i].x = __expf(v[i].x - m);
        v[i].y = __expf(v[i].y - m);
        v[i].z = __expf(v[i].z - m);
        v[i].w = __expf(v[i].w - m);
        s += v[i].x + v[i].y + v[i].z + v[i].w;
    }
    #pragma unroll
    for (int o = 16; o; o >>= 1) s += __shfl_xor_sync(0xffffffffu, s, o);
    if ((tid & 31) == 0) reds[tid >> 5] = s;
    __syncthreads();
    s = 0.f;
    #pragma unroll
    for (int i = 0; i < 8; i++) s += reds[i];

    const float inv = 1.0f / s;
    #pragma unroll
    for (int i = 0; i < 4; i++) {
        v[i].x *= inv; v[i].y *= inv; v[i].z *= inv; v[i].w *= inv;
        p[tid + i * 256] = v[i];
    }
}

// ---------------------------------------------------------------------------
// Launch: x->(Q,K,V) projections, S = 0.5*Q@K^T, softmax rows, Z = P@V
// ---------------------------------------------------------------------------
extern "C" void kernel_launch(void* const* d_in, const int* /*in_sizes*/, int /*n_in*/,
                              void* d_out, int /*out_size*/)
{
    const float* x  = (const float*)d_in[0];
    const float* Wq = (const float*)d_in[1];
    const float* bq = (const float*)d_in[2];
    const float* Wk = (const float*)d_in[3];
    const float* bk = (const float*)d_in[4];
    const float* Wv = (const float*)d_in[5];
    const float* bv = (const float*)d_in[6];
    float* out = (float*)d_out;

    float *Q, *K, *V, *P;
    cudaGetSymbolAddress((void**)&Q, g_Q);
    cudaGetSymbolAddress((void**)&K, g_K);
    cudaGetSymbolAddress((void**)&V, g_V);
    cudaGetSymbolAddress((void**)&P, g_P);

    const long long dQKV = (long long)S_ * D_;  // per-batch Q/K/V stride
    const long long dP   = (long long)S_ * S_;  // per-batch score stride

    dim3 blk(256);

    // QKV projections: M = B*S = 16384, N = K = 512 (NN, +bias)
    dim3 gProj(D_ / 128, (B_ * S_) / 128, 1);
    gemm128<false, true><<<gProj, blk>>>(x, Wq, bq, Q, B_ * S_, D_, D_, 0, 0, 0, 1.f);
    gemm128<false, true><<<gProj, blk>>>(x, Wk, bk, K, B_ * S_, D_, D_, 0, 0, 0, 1.f);
    gemm128<false, true><<<gProj, blk>>>(x, Wv, bv, V, B_ * S_, D_, D_, 0, 0, 0, 1.f);

    // Scores: per-batch 4096x4096x512, NT, alpha = 1/scale = 0.5
    dim3 gS(S_ / 128, S_ / 128, B_);
    gemm128<true, false><<<gS, blk>>>(Q, K, nullptr, P, S_, S_, D_, dQKV, dQKV, dP, 0.5f);

    // Row softmax (in place)
    softmax4096<<<B_ * S_, 256>>>(P);

    // Z = P @ V: per-batch 4096x512x4096, NN
    dim3 gZ(D_ / 128, S_ / 128, B_);
    gemm128<false, false><<<gZ, blk>>>(P, V, nullptr, out, S_, D_, S_, dP, dQKV, dQKV, 1.f);
}